// round 2
// baseline (speedup 1.0000x reference)
#include <cuda_runtime.h>
#include <math.h>
#include <stdint.h>

#define K_CL 1024
#define DM   256
#define NPX  65536
#define NISO 12
#define GRX  304   // 2 blocks/SM * 152 SMs

// ---------------- device scratch (no allocations allowed) ----------------
__device__ float g_part[2 * GRX * 15 * K_CL];   // per-block partial sums
__device__ float g_S[2 * 15 * K_CL];            // reduced stats [mat][c][k]
__device__ float g_GU[K_CL * 32];
__device__ float g_GV[K_CL * 32];
__device__ float g_HA[K_CL * 32];
__device__ float g_HB[K_CL * 32];
__device__ float g_QC[K_CL * 2];
__device__ float g_KC[K_CL * 2];
__device__ float g_R[K_CL * K_CL];
__device__ float g_L[K_CL * K_CL];              // logits, then attn (in-place softmax)
__device__ float g_AO[K_CL * DM];               // attn @ key_emb
__device__ float g_X[K_CL * DM];                // after LN1
__device__ float g_F1[K_CL * 4 * DM];           // FFN hidden (1024x1024)
__device__ float g_F2[K_CL * DM];               // FFN out

// ---------------- kernel 1: fused A^T reductions (HBM bound) ----------------
// For each assignment matrix: accumulate per-cluster {sum(a*x), sum(a*y), sum(a),
// sum(a per iso class)}. Thread owns k = tid + 256*j (j=0..3). x/y/sum in regs,
// iso buckets in smem [12][1024] (conflict-free, exclusive ownership).
__launch_bounds__(256)
__global__ void reduce_k(const float* __restrict__ qA, const float* __restrict__ kA,
                         const float* __restrict__ qco, const float* __restrict__ kco,
                         const int* __restrict__ qiso, const int* __restrict__ kiso)
{
    __shared__ float sIso[NISO * K_CL];   // 48KB exactly
    const int tid = threadIdx.x;
    const int bx  = blockIdx.x;
    const int mat = blockIdx.y;
    const float* __restrict__ A   = mat ? kA   : qA;
    const float* __restrict__ co  = mat ? kco  : qco;
    const int*   __restrict__ iso = mat ? kiso : qiso;

    for (int i = tid; i < NISO * K_CL; i += 256) sIso[i] = 0.f;
    __syncthreads();

    float sx[4] = {0,0,0,0}, sy[4] = {0,0,0,0}, ss[4] = {0,0,0,0};

    for (int r = bx; r < NPX; r += GRX) {
        const float x = co[2*r];
        const float y = co[2*r+1];
        const int   c = iso[r] - 1;
        float* isoRow = sIso + c * K_CL + tid;
        const float* Ar = A + (size_t)r * K_CL + tid;
        #pragma unroll
        for (int j = 0; j < 4; j++) {
            float a = Ar[j * 256];
            sx[j] = fmaf(a, x, sx[j]);
            sy[j] = fmaf(a, y, sy[j]);
            ss[j] += a;
            isoRow[j * 256] += a;
        }
    }
    __syncthreads();

    float* P = g_part + (size_t)(mat * GRX + bx) * 15 * K_CL;
    #pragma unroll
    for (int j = 0; j < 4; j++) {
        int k = tid + j * 256;
        P[0 * K_CL + k] = sx[j];
        P[1 * K_CL + k] = sy[j];
        P[2 * K_CL + k] = ss[j];
    }
    for (int c = 0; c < NISO; c++)
        #pragma unroll
        for (int j = 0; j < 4; j++) {
            int k = tid + j * 256;
            P[(3 + c) * K_CL + k] = sIso[c * K_CL + k];
        }
}

// ---------------- kernel 2: reduce partials across blocks ----------------
__global__ void reduce2_k()
{
    int idx = blockIdx.x * 256 + threadIdx.x;      // 0..30719
    int mat = idx / (15 * K_CL);
    int rem = idx % (15 * K_CL);
    const float* P = g_part + (size_t)mat * GRX * 15 * K_CL + rem;
    float s = 0.f;
    for (int b = 0; b < GRX; b++) s += P[(size_t)b * 15 * K_CL];
    g_S[idx] = s;
}

// ---------------- kernel 3: per-cluster features + MLP-layer-1 factorization ----------------
__global__ void cfeat_k(const float* __restrict__ sensor,
                        const float* __restrict__ g1w, const float* __restrict__ g1b,
                        const float* __restrict__ h1w, const float* __restrict__ h1b)
{
    int k = blockIdx.x * 256 + threadIdx.x;
    float dq[NISO], dkp[NISO];

    float sq  = g_S[(0*15 + 2)*K_CL + k];
    float qcx = g_S[(0*15 + 0)*K_CL + k] / (sq + 1e-6f);
    float qcy = g_S[(0*15 + 1)*K_CL + k] / (sq + 1e-6f);
    float sk  = g_S[(1*15 + 2)*K_CL + k];
    float kcx = g_S[(1*15 + 0)*K_CL + k] / (sk + 1e-6f);
    float kcy = g_S[(1*15 + 1)*K_CL + k] / (sk + 1e-6f);

    float sum0 = 0.f, sum1 = 0.f;
    #pragma unroll
    for (int c = 0; c < NISO; c++) {
        dq[c]  = g_S[(0*15 + 3 + c)*K_CL + k];  sum0 += dq[c];
        dkp[c] = g_S[(1*15 + 3 + c)*K_CL + k];  sum1 += dkp[c];
    }
    #pragma unroll
    for (int c = 0; c < NISO; c++) { dq[c] /= sum0; dkp[c] /= sum1; }

    float sxn = sensor[0], syn = sensor[1];
    float nks  = sqrtf((qcx - sxn)*(qcx - sxn) + (qcy - syn)*(qcy - syn));
    float nkps = sqrtf((kcx - sxn)*(kcx - sxn) + (kcy - syn)*(kcy - syn));

    g_QC[2*k] = qcx; g_QC[2*k+1] = qcy;
    g_KC[2*k] = kcx; g_KC[2*k+1] = kcy;

    for (int o = 0; o < 32; o++) {
        float u = g1b[o], v = 0.f;
        #pragma unroll
        for (int c = 0; c < NISO; c++) {
            u = fmaf(dq[c],  g1w[c*32 + o],           u);
            v = fmaf(dkp[c], g1w[(NISO + c)*32 + o],  v);
        }
        g_GU[k*32 + o] = u;
        g_GV[k*32 + o] = v;
        g_HA[k*32 + o] = fmaf(nks, h1w[32 + o], h1b[o]);   // n_ks * h1_w[1] + b
        g_HB[k*32 + o] = nkps * h1w[64 + o];               // n_kps * h1_w[2]
    }
}

// ---------------- kernel 4: R factor over KxK pairs ----------------
__launch_bounds__(256)
__global__ void rfactor_k(const float* __restrict__ g2w, const float* __restrict__ g2b,
                          const float* __restrict__ h2w, const float* __restrict__ h2b,
                          const float* __restrict__ h1w)
{
    __shared__ float sGU[32][33], sGV[32][33], sHA[32][33], sHB[32][33];
    __shared__ float sW[96];            // [0:32)=g2w, [32:64)=h2w, [64:96)=h1w row0
    __shared__ float sQC[32][2], sKC[32][2];

    const int tid = threadIdx.x;
    const int ib = blockIdx.y * 32, jb = blockIdx.x * 32;

    {
        int row = tid >> 3, c0 = (tid & 7) * 4;
        float4 u = *(const float4*)&g_GU[(ib + row)*32 + c0];
        sGU[row][c0] = u.x; sGU[row][c0+1] = u.y; sGU[row][c0+2] = u.z; sGU[row][c0+3] = u.w;
        float4 v = *(const float4*)&g_GV[(jb + row)*32 + c0];
        sGV[row][c0] = v.x; sGV[row][c0+1] = v.y; sGV[row][c0+2] = v.z; sGV[row][c0+3] = v.w;
        float4 a = *(const float4*)&g_HA[(ib + row)*32 + c0];
        sHA[row][c0] = a.x; sHA[row][c0+1] = a.y; sHA[row][c0+2] = a.z; sHA[row][c0+3] = a.w;
        float4 b = *(const float4*)&g_HB[(jb + row)*32 + c0];
        sHB[row][c0] = b.x; sHB[row][c0+1] = b.y; sHB[row][c0+2] = b.z; sHB[row][c0+3] = b.w;
    }
    if (tid < 32)       sW[tid] = g2w[tid];
    else if (tid < 64)  sW[tid] = h2w[tid - 32];
    else if (tid < 96)  sW[tid] = h1w[tid - 64];
    if (tid < 64) {
        sQC[tid>>1][tid&1] = g_QC[(ib + (tid>>1))*2 + (tid&1)];
        sKC[tid>>1][tid&1] = g_KC[(jb + (tid>>1))*2 + (tid&1)];
    }
    __syncthreads();

    const int j = tid & 31, i0 = tid >> 5;
    float gv[32], hb[32];
    #pragma unroll
    for (int c = 0; c < 32; c++) { gv[c] = sGV[j][c]; hb[c] = sHB[j][c]; }
    const float kcx = sKC[j][0], kcy = sKC[j][1];
    const float g2b0 = g2b[0], h2b0 = h2b[0];

    #pragma unroll
    for (int m = 0; m < 4; m++) {
        int ii = i0 * 4 + m;
        float dx = sQC[ii][0] - kcx, dy = sQC[ii][1] - kcy;
        float nkk = sqrtf(dx*dx + dy*dy);
        float ga = 0.f, ha = 0.f;
        #pragma unroll
        for (int c = 0; c < 32; c++) {
            float gt = fmaxf(sGU[ii][c] + gv[c], 0.f);
            ga = fmaf(gt, sW[c], ga);
            float ht = fmaxf(fmaf(nkk, sW[64 + c], sHA[ii][c] + hb[c]), 0.f);
            ha = fmaf(ht, sW[32 + c], ha);
        }
        float G = fmaxf(ga + g2b0, 0.f);
        float H = fmaxf(ha + h2b0, 0.f);
        g_R[(size_t)(ib + ii) * K_CL + jb + j] = G * H;
    }
}

// ---------------- generic tiled fp32 GEMM ----------------
// C(MxN) = A(MxKd) @ op(B); BT: B stored (N,Kd) row-major (C=A@B^T).
// MODE 0: store; 1: *scale*ext[i*N+j]; 2: relu(+ext[j]); 3: +ext[j].
template<int TM, int TN, int MODE, bool BT>
__launch_bounds__(256)
__global__ void gemm_k(const float* __restrict__ A, const float* __restrict__ B,
                       float* __restrict__ C, int M, int N, int Kd,
                       const float* __restrict__ ext, float scale)
{
    constexpr int RM = TM / 16, RN = TN / 16;
    __shared__ float As[16][TM];
    __shared__ float Bs[16][TN];
    const int tid = threadIdx.x;
    const int tx = tid & 15, ty = tid >> 4;
    const int row0 = blockIdx.y * TM, col0 = blockIdx.x * TN;

    float acc[RM][RN];
    #pragma unroll
    for (int m = 0; m < RM; m++)
        #pragma unroll
        for (int n = 0; n < RN; n++) acc[m][n] = 0.f;

    for (int k0 = 0; k0 < Kd; k0 += 16) {
        {   // A tile: TM rows x 16 k, one float4 per participating thread
            int lr = tid >> 2, lc = (tid & 3) * 4;
            if (TM * 4 >= 256 || tid < TM * 4) {
                float4 v = *(const float4*)(A + (size_t)(row0 + lr) * Kd + k0 + lc);
                As[lc+0][lr] = v.x; As[lc+1][lr] = v.y; As[lc+2][lr] = v.z; As[lc+3][lr] = v.w;
            }
        }
        if (BT) {
            int lr = tid >> 2, lc = (tid & 3) * 4;
            if (TN * 4 >= 256 || tid < TN * 4) {
                float4 v = *(const float4*)(B + (size_t)(col0 + lr) * Kd + k0 + lc);
                Bs[lc+0][lr] = v.x; Bs[lc+1][lr] = v.y; Bs[lc+2][lr] = v.z; Bs[lc+3][lr] = v.w;
            }
        } else {
            constexpr int PER_ROW = TN / 4;
            int lr = tid / PER_ROW, lc = (tid % PER_ROW) * 4;
            if (4 * TN >= 256 || tid < 4 * TN) {
                float4 v = *(const float4*)(B + (size_t)(k0 + lr) * N + col0 + lc);
                *(float4*)&Bs[lr][lc] = v;
            }
        }
        __syncthreads();
        #pragma unroll
        for (int kk = 0; kk < 16; kk++) {
            float a[RM], b[RN];
            if constexpr (RM == 4) {
                float4 t = *(const float4*)&As[kk][ty * 4];
                a[0] = t.x; a[1] = t.y; a[2] = t.z; a[3] = t.w;
            } else {
                float2 t = *(const float2*)&As[kk][ty * 2];
                a[0] = t.x; a[1] = t.y;
            }
            {
                float4 t = *(const float4*)&Bs[kk][tx * 4];
                b[0] = t.x; b[1] = t.y; b[2] = t.z; b[3] = t.w;
            }
            #pragma unroll
            for (int m = 0; m < RM; m++)
                #pragma unroll
                for (int n = 0; n < RN; n++)
                    acc[m][n] = fmaf(a[m], b[n], acc[m][n]);
        }
        __syncthreads();
    }

    #pragma unroll
    for (int m = 0; m < RM; m++) {
        int i = row0 + ty * RM + m;
        #pragma unroll
        for (int n = 0; n < RN; n++) {
            int j = col0 + tx * RN + n;
            float v = acc[m][n];
            if (MODE == 1)      v = v * scale * ext[(size_t)i * N + j];
            else if (MODE == 2) v = fmaxf(v + ext[j], 0.f);
            else if (MODE == 3) v = v + ext[j];
            C[(size_t)i * N + j] = v;
        }
    }
}

// ---------------- softmax (row-wise, in place, 1024 cols) ----------------
__global__ void softmax_k(float* __restrict__ X)
{
    const int row = blockIdx.x, tid = threadIdx.x;
    __shared__ float red[256];
    float v[4];
    float m = -3.4e38f;
    #pragma unroll
    for (int j = 0; j < 4; j++) { v[j] = X[(size_t)row * K_CL + tid + j * 256]; m = fmaxf(m, v[j]); }
    red[tid] = m; __syncthreads();
    #pragma unroll
    for (int s = 128; s > 0; s >>= 1) { if (tid < s) red[tid] = fmaxf(red[tid], red[tid + s]); __syncthreads(); }
    m = red[0]; __syncthreads();
    float sum = 0.f;
    #pragma unroll
    for (int j = 0; j < 4; j++) { v[j] = expf(v[j] - m); sum += v[j]; }
    red[tid] = sum; __syncthreads();
    #pragma unroll
    for (int s = 128; s > 0; s >>= 1) { if (tid < s) red[tid] += red[tid + s]; __syncthreads(); }
    float inv = 1.f / red[0];
    #pragma unroll
    for (int j = 0; j < 4; j++) X[(size_t)row * K_CL + tid + j * 256] = v[j] * inv;
}

// ---------------- residual add + LayerNorm (256 cols) ----------------
__global__ void add_ln_k(const float* __restrict__ a, const float* __restrict__ b,
                         const float* __restrict__ g, const float* __restrict__ be,
                         float* __restrict__ out)
{
    const int row = blockIdx.x, tid = threadIdx.x;
    __shared__ float red[256];
    float x = a[row * DM + tid] + b[row * DM + tid];
    red[tid] = x; __syncthreads();
    #pragma unroll
    for (int s = 128; s > 0; s >>= 1) { if (tid < s) red[tid] += red[tid + s]; __syncthreads(); }
    float mean = red[0] * (1.f / DM); __syncthreads();
    float d = x - mean;
    red[tid] = d * d; __syncthreads();
    #pragma unroll
    for (int s = 128; s > 0; s >>= 1) { if (tid < s) red[tid] += red[tid + s]; __syncthreads(); }
    float var = red[0] * (1.f / DM);
    out[row * DM + tid] = d * rsqrtf(var + 1e-6f) * g[tid] + be[tid];
}

// ---------------- launch ----------------
extern "C" void kernel_launch(void* const* d_in, const int* in_sizes, int n_in,
                              void* d_out, int out_size)
{
    const float* sensor = (const float*)d_in[0];
    const float* query  = (const float*)d_in[1];
    const float* keyemb = (const float*)d_in[2];
    const float* qA     = (const float*)d_in[3];
    const float* kA     = (const float*)d_in[4];
    const float* qco    = (const float*)d_in[5];
    const float* kco    = (const float*)d_in[6];
    const int*   qiso   = (const int*)d_in[7];
    const int*   kiso   = (const int*)d_in[8];
    const float* g1w    = (const float*)d_in[9];
    const float* g1b    = (const float*)d_in[10];
    const float* g2w    = (const float*)d_in[11];
    const float* g2b    = (const float*)d_in[12];
    const float* h1w    = (const float*)d_in[13];
    const float* h1b    = (const float*)d_in[14];
    const float* h2w    = (const float*)d_in[15];
    const float* h2b    = (const float*)d_in[16];
    const float* f1w    = (const float*)d_in[17];
    const float* f1b    = (const float*)d_in[18];
    const float* f2w    = (const float*)d_in[19];
    const float* f2b    = (const float*)d_in[20];
    const float* ln1g   = (const float*)d_in[21];
    const float* ln1b   = (const float*)d_in[22];
    const float* ln2g   = (const float*)d_in[23];
    const float* ln2b   = (const float*)d_in[24];
    float* out = (float*)d_out;

    float *pR, *pL, *pAO, *pX, *pF1, *pF2;
    cudaGetSymbolAddress((void**)&pR,  g_R);
    cudaGetSymbolAddress((void**)&pL,  g_L);
    cudaGetSymbolAddress((void**)&pAO, g_AO);
    cudaGetSymbolAddress((void**)&pX,  g_X);
    cudaGetSymbolAddress((void**)&pF1, g_F1);
    cudaGetSymbolAddress((void**)&pF2, g_F2);

    // 1) fused transposed reductions over N=65536 (the HBM-bound pass)
    reduce_k<<<dim3(GRX, 2), 256>>>(qA, kA, qco, kco, qiso, kiso);
    reduce2_k<<<(2 * 15 * K_CL) / 256, 256>>>();

    // 2) per-cluster features + factorized MLP layer-1 partials
    cfeat_k<<<K_CL / 256, 256>>>(sensor, g1w, g1b, h1w, h1b);

    // 3) R factor over all KxK pairs
    rfactor_k<<<dim3(32, 32), 256>>>(g2w, g2b, h2w, h2b, h1w);

    // 4) logits = (Q @ K^T) / 16 * R
    gemm_k<64, 64, 1, true><<<dim3(16, 16), 256>>>(query, keyemb, pL, K_CL, K_CL, DM, pR, 0.0625f);

    // 5) softmax rows
    softmax_k<<<K_CL, 256>>>(pL);

    // 6) attn @ key_emb
    gemm_k<32, 64, 0, false><<<dim3(4, 32), 256>>>(pL, keyemb, pAO, K_CL, DM, K_CL, nullptr, 1.f);

    // 7) x = LN1(query + attn_out)
    add_ln_k<<<K_CL, 256>>>(query, pAO, ln1g, ln1b, pX);

    // 8) FFN1: relu(x @ w1 + b1)
    gemm_k<64, 64, 2, false><<<dim3(16, 16), 256>>>(pX, f1w, pF1, K_CL, 4 * DM, DM, f1b, 1.f);

    // 9) FFN2: h @ w2 + b2
    gemm_k<32, 64, 3, false><<<dim3(4, 32), 256>>>(pF1, f2w, pF2, K_CL, DM, 4 * DM, f2b, 1.f);

    // 10) out = LN2(x + ffn)
    add_ln_k<<<K_CL, 256>>>(pX, pF2, ln2g, ln2b, out);
}

// round 3
// speedup vs baseline: 1.0351x; 1.0351x over previous
#include <cuda_runtime.h>
#include <math.h>
#include <stdint.h>

#define K_CL 1024
#define DM   256
#define NPX  65536
#define NISO 12
#define RBLK 304      // blocks per matrix in reduce_k
#define CHUNK 216     // rows per reduce block (304*216 >= 65536)

// ---------------- device scratch ----------------
__device__ float g_part[2 * RBLK * 15 * K_CL];
__device__ float g_S[2 * 15 * K_CL];
__device__ float g_GU[K_CL * 32];
__device__ float g_GV[K_CL * 32];
__device__ float g_HA[K_CL * 32];
__device__ float g_HB[K_CL * 32];
__device__ float g_QC[K_CL * 2];
__device__ float g_KC[K_CL * 2];
__device__ float g_R[K_CL * K_CL];
__device__ float g_L[K_CL * K_CL];
__device__ float g_AO[K_CL * DM];
__device__ float g_X[K_CL * DM];
__device__ float g_F1[K_CL * 4 * DM];
__device__ float g_F2[K_CL * DM];

// ---------------- kernel 1: fused A^T reductions (HBM bound) ----------------
// Thread owns k = tid*4..tid*4+3 (one float4 per row). x/y/sum in regs,
// iso buckets as float4 in smem (exclusive per-thread slots, LDS.128/STS.128).
__launch_bounds__(256)
__global__ void reduce_k(const float* __restrict__ qA, const float* __restrict__ kA,
                         const float* __restrict__ qco, const float* __restrict__ kco,
                         const int* __restrict__ qiso, const int* __restrict__ kiso)
{
    __shared__ float4 sIso[NISO * 256];   // 48KB exactly
    const int tid = threadIdx.x;
    const int bx  = blockIdx.x;
    const int mat = blockIdx.y;
    const float* __restrict__ A   = mat ? kA   : qA;
    const float* __restrict__ co  = mat ? kco  : qco;
    const int*   __restrict__ iso = mat ? kiso : qiso;

    #pragma unroll
    for (int i = tid; i < NISO * 256; i += 256) sIso[i] = make_float4(0.f, 0.f, 0.f, 0.f);
    __syncthreads();

    float4 sx = make_float4(0,0,0,0), sy = sx, ss = sx;

    const int base = bx * CHUNK;
    const int end  = (base + CHUNK < NPX) ? base + CHUNK : NPX;
    const float4* __restrict__ A4 = (const float4*)A;

    #pragma unroll 4
    for (int r = base; r < end; r++) {
        const float x = __ldg(co + 2*r);
        const float y = __ldg(co + 2*r + 1);
        const int   c = __ldg(iso + r) - 1;
        float4 a = A4[(size_t)r * 256 + tid];
        sx.x = fmaf(a.x, x, sx.x); sx.y = fmaf(a.y, x, sx.y);
        sx.z = fmaf(a.z, x, sx.z); sx.w = fmaf(a.w, x, sx.w);
        sy.x = fmaf(a.x, y, sy.x); sy.y = fmaf(a.y, y, sy.y);
        sy.z = fmaf(a.z, y, sy.z); sy.w = fmaf(a.w, y, sy.w);
        ss.x += a.x; ss.y += a.y; ss.z += a.z; ss.w += a.w;
        float4 t = sIso[c * 256 + tid];
        t.x += a.x; t.y += a.y; t.z += a.z; t.w += a.w;
        sIso[c * 256 + tid] = t;
    }

    float4* P4 = (float4*)(g_part + (size_t)(mat * RBLK + bx) * 15 * K_CL);
    P4[0 * 256 + tid] = sx;
    P4[1 * 256 + tid] = sy;
    P4[2 * 256 + tid] = ss;
    #pragma unroll
    for (int c = 0; c < NISO; c++)
        P4[(3 + c) * 256 + tid] = sIso[c * 256 + tid];
}

// ---------------- kernel 2: reduce partials across blocks ----------------
__global__ void reduce2_k()
{
    int idx = blockIdx.x * 256 + threadIdx.x;       // 0..30719
    int mat = idx / (15 * K_CL);
    int rem = idx % (15 * K_CL);
    const float* P = g_part + (size_t)mat * RBLK * 15 * K_CL + rem;
    float s = 0.f;
    #pragma unroll 8
    for (int b = 0; b < RBLK; b++) s += P[(size_t)b * 15 * K_CL];
    g_S[idx] = s;
}

// ---------------- kernel 3: per-cluster features + layer-1 factorization ----------------
__global__ void cfeat_k(const float* __restrict__ sensor,
                        const float* __restrict__ g1w, const float* __restrict__ g1b,
                        const float* __restrict__ h1w, const float* __restrict__ h1b)
{
    int k = blockIdx.x * 256 + threadIdx.x;
    float dq[NISO], dkp[NISO];

    float sq  = g_S[(0*15 + 2)*K_CL + k];
    float qcx = g_S[(0*15 + 0)*K_CL + k] / (sq + 1e-6f);
    float qcy = g_S[(0*15 + 1)*K_CL + k] / (sq + 1e-6f);
    float sk  = g_S[(1*15 + 2)*K_CL + k];
    float kcx = g_S[(1*15 + 0)*K_CL + k] / (sk + 1e-6f);
    float kcy = g_S[(1*15 + 1)*K_CL + k] / (sk + 1e-6f);

    float sum0 = 0.f, sum1 = 0.f;
    #pragma unroll
    for (int c = 0; c < NISO; c++) {
        dq[c]  = g_S[(0*15 + 3 + c)*K_CL + k];  sum0 += dq[c];
        dkp[c] = g_S[(1*15 + 3 + c)*K_CL + k];  sum1 += dkp[c];
    }
    #pragma unroll
    for (int c = 0; c < NISO; c++) { dq[c] /= sum0; dkp[c] /= sum1; }

    float sxn = sensor[0], syn = sensor[1];
    float nks  = sqrtf((qcx - sxn)*(qcx - sxn) + (qcy - syn)*(qcy - syn));
    float nkps = sqrtf((kcx - sxn)*(kcx - sxn) + (kcy - syn)*(kcy - syn));

    g_QC[2*k] = qcx; g_QC[2*k+1] = qcy;
    g_KC[2*k] = kcx; g_KC[2*k+1] = kcy;

    for (int o = 0; o < 32; o++) {
        float u = g1b[o], v = 0.f;
        #pragma unroll
        for (int c = 0; c < NISO; c++) {
            u = fmaf(dq[c],  g1w[c*32 + o],          u);
            v = fmaf(dkp[c], g1w[(NISO + c)*32 + o], v);
        }
        g_GU[k*32 + o] = u;
        g_GV[k*32 + o] = v;
        g_HA[k*32 + o] = fmaf(nks, h1w[32 + o], h1b[o]);
        g_HB[k*32 + o] = nkps * h1w[64 + o];
    }
}

// ---------------- kernel 4: R factor, GEMM-style (64x64 tile, 4x4/thread) ----------------
__launch_bounds__(256)
__global__ void rfactor_k(const float* __restrict__ g2w, const float* __restrict__ g2b,
                          const float* __restrict__ h2w, const float* __restrict__ h2b,
                          const float* __restrict__ h1w)
{
    __shared__ float sGU[64][33], sGV[64][33], sHA[64][33], sHB[64][33];
    __shared__ float sW[96];
    __shared__ float sQC[64][2], sKC[64][2];

    const int tid = threadIdx.x;
    const int ib = blockIdx.y * 64, jb = blockIdx.x * 64;

    #pragma unroll
    for (int p = 0; p < 2; p++) {
        int idx = tid + p * 256;
        int row = idx >> 3, c0 = (idx & 7) * 4;
        float4 u = *(const float4*)&g_GU[(ib + row)*32 + c0];
        sGU[row][c0] = u.x; sGU[row][c0+1] = u.y; sGU[row][c0+2] = u.z; sGU[row][c0+3] = u.w;
        float4 v = *(const float4*)&g_GV[(jb + row)*32 + c0];
        sGV[row][c0] = v.x; sGV[row][c0+1] = v.y; sGV[row][c0+2] = v.z; sGV[row][c0+3] = v.w;
        float4 a = *(const float4*)&g_HA[(ib + row)*32 + c0];
        sHA[row][c0] = a.x; sHA[row][c0+1] = a.y; sHA[row][c0+2] = a.z; sHA[row][c0+3] = a.w;
        float4 b = *(const float4*)&g_HB[(jb + row)*32 + c0];
        sHB[row][c0] = b.x; sHB[row][c0+1] = b.y; sHB[row][c0+2] = b.z; sHB[row][c0+3] = b.w;
    }
    if (tid < 32)       sW[tid] = g2w[tid];
    else if (tid < 64)  sW[tid] = h2w[tid - 32];
    else if (tid < 96)  sW[tid] = h1w[tid - 64];
    if (tid < 128)      sQC[tid >> 1][tid & 1] = g_QC[(ib + (tid >> 1))*2 + (tid & 1)];
    else                { int t = tid - 128; sKC[t >> 1][t & 1] = g_KC[(jb + (t >> 1))*2 + (t & 1)]; }
    __syncthreads();

    const int ty = tid >> 4, tx = tid & 15;
    float nkk[4][4];
    #pragma unroll
    for (int m = 0; m < 4; m++) {
        float qx = sQC[ty*4 + m][0], qy = sQC[ty*4 + m][1];
        #pragma unroll
        for (int n = 0; n < 4; n++) {
            float dx = qx - sKC[tx*4 + n][0], dy = qy - sKC[tx*4 + n][1];
            nkk[m][n] = sqrtf(dx*dx + dy*dy);
        }
    }

    float gacc[4][4], hacc[4][4];
    #pragma unroll
    for (int m = 0; m < 4; m++)
        #pragma unroll
        for (int n = 0; n < 4; n++) { gacc[m][n] = 0.f; hacc[m][n] = 0.f; }

    #pragma unroll 4
    for (int c = 0; c < 32; c++) {
        float gw = sW[c], hw = sW[32 + c], w1c = sW[64 + c];
        float au[4], aa[4], bv[4], bb[4];
        #pragma unroll
        for (int m = 0; m < 4; m++) { au[m] = sGU[ty*4 + m][c]; aa[m] = sHA[ty*4 + m][c]; }
        #pragma unroll
        for (int n = 0; n < 4; n++) { bv[n] = sGV[tx*4 + n][c]; bb[n] = sHB[tx*4 + n][c]; }
        #pragma unroll
        for (int m = 0; m < 4; m++)
            #pragma unroll
            for (int n = 0; n < 4; n++) {
                float g = fmaxf(au[m] + bv[n], 0.f);
                gacc[m][n] = fmaf(g, gw, gacc[m][n]);
                float h = fmaxf(fmaf(nkk[m][n], w1c, aa[m] + bb[n]), 0.f);
                hacc[m][n] = fmaf(h, hw, hacc[m][n]);
            }
    }

    const float g2b0 = g2b[0], h2b0 = h2b[0];
    #pragma unroll
    for (int m = 0; m < 4; m++) {
        float4 o;
        float* op = &o.x;
        #pragma unroll
        for (int n = 0; n < 4; n++)
            op[n] = fmaxf(gacc[m][n] + g2b0, 0.f) * fmaxf(hacc[m][n] + h2b0, 0.f);
        *(float4*)&g_R[(size_t)(ib + ty*4 + m) * K_CL + jb + tx*4] = o;
    }
}

// ---------------- generic tiled fp32 GEMM ----------------
// C(MxN) = A(MxKd) @ op(B); BT: B stored (N,Kd) row-major (C=A@B^T).
// MODE 0: store; 1: *scale*ext[i*N+j]; 2: relu(+ext[j]); 3: +ext[j].
template<int TM, int TN, int MODE, bool BT>
__launch_bounds__(256)
__global__ void gemm_k(const float* __restrict__ A, const float* __restrict__ B,
                       float* __restrict__ C, int M, int N, int Kd,
                       const float* __restrict__ ext, float scale)
{
    constexpr int RM = TM / 16, RN = TN / 16;
    __shared__ float As[16][TM];
    __shared__ float Bs[16][TN];
    const int tid = threadIdx.x;
    const int tx = tid & 15, ty = tid >> 4;
    const int row0 = blockIdx.y * TM, col0 = blockIdx.x * TN;

    float acc[RM][RN];
    #pragma unroll
    for (int m = 0; m < RM; m++)
        #pragma unroll
        for (int n = 0; n < RN; n++) acc[m][n] = 0.f;

    for (int k0 = 0; k0 < Kd; k0 += 16) {
        #pragma unroll
        for (int idx = tid; idx < TM * 4; idx += 256) {
            int lr = idx >> 2, lc = (idx & 3) * 4;
            float4 v = *(const float4*)(A + (size_t)(row0 + lr) * Kd + k0 + lc);
            As[lc+0][lr] = v.x; As[lc+1][lr] = v.y; As[lc+2][lr] = v.z; As[lc+3][lr] = v.w;
        }
        if (BT) {
            #pragma unroll
            for (int idx = tid; idx < TN * 4; idx += 256) {
                int lr = idx >> 2, lc = (idx & 3) * 4;
                float4 v = *(const float4*)(B + (size_t)(col0 + lr) * Kd + k0 + lc);
                Bs[lc+0][lr] = v.x; Bs[lc+1][lr] = v.y; Bs[lc+2][lr] = v.z; Bs[lc+3][lr] = v.w;
            }
        } else {
            #pragma unroll
            for (int idx = tid; idx < TN * 4; idx += 256) {
                int lr = idx / (TN / 4), lc = (idx % (TN / 4)) * 4;
                float4 v = *(const float4*)(B + (size_t)(k0 + lr) * N + col0 + lc);
                *(float4*)&Bs[lr][lc] = v;
            }
        }
        __syncthreads();
        #pragma unroll
        for (int kk = 0; kk < 16; kk++) {
            float a[RM], b[RN];
            if constexpr (RM == 2) {
                float2 t = *(const float2*)&As[kk][ty * 2];
                a[0] = t.x; a[1] = t.y;
            } else {
                #pragma unroll
                for (int q = 0; q < RM; q += 4) {
                    float4 t = *(const float4*)&As[kk][ty * RM + q];
                    a[q] = t.x; a[q+1] = t.y; a[q+2] = t.z; a[q+3] = t.w;
                }
            }
            {
                float4 t = *(const float4*)&Bs[kk][tx * 4];
                b[0] = t.x; b[1] = t.y; b[2] = t.z; b[3] = t.w;
            }
            #pragma unroll
            for (int m = 0; m < RM; m++)
                #pragma unroll
                for (int n = 0; n < RN; n++)
                    acc[m][n] = fmaf(a[m], b[n], acc[m][n]);
        }
        __syncthreads();
    }

    #pragma unroll
    for (int m = 0; m < RM; m++) {
        int i = row0 + ty * RM + m;
        #pragma unroll
        for (int n = 0; n < RN; n++) {
            int j = col0 + tx * RN + n;
            float v = acc[m][n];
            if (MODE == 1)      v = v * scale * ext[(size_t)i * N + j];
            else if (MODE == 2) v = fmaxf(v + ext[j], 0.f);
            else if (MODE == 3) v = v + ext[j];
            C[(size_t)i * N + j] = v;
        }
    }
}

// ---------------- softmax (row-wise, in place, 1024 cols) ----------------
__global__ void softmax_k(float* __restrict__ X)
{
    const int row = blockIdx.x, tid = threadIdx.x;
    __shared__ float red[256];
    float v[4];
    float m = -3.4e38f;
    #pragma unroll
    for (int j = 0; j < 4; j++) { v[j] = X[(size_t)row * K_CL + tid + j * 256]; m = fmaxf(m, v[j]); }
    red[tid] = m; __syncthreads();
    #pragma unroll
    for (int s = 128; s > 0; s >>= 1) { if (tid < s) red[tid] = fmaxf(red[tid], red[tid + s]); __syncthreads(); }
    m = red[0]; __syncthreads();
    float sum = 0.f;
    #pragma unroll
    for (int j = 0; j < 4; j++) { v[j] = __expf(v[j] - m); sum += v[j]; }
    red[tid] = sum; __syncthreads();
    #pragma unroll
    for (int s = 128; s > 0; s >>= 1) { if (tid < s) red[tid] += red[tid + s]; __syncthreads(); }
    float inv = 1.f / red[0];
    #pragma unroll
    for (int j = 0; j < 4; j++) X[(size_t)row * K_CL + tid + j * 256] = v[j] * inv;
}

// ---------------- residual add + LayerNorm (256 cols) ----------------
__global__ void add_ln_k(const float* __restrict__ a, const float* __restrict__ b,
                         const float* __restrict__ g, const float* __restrict__ be,
                         float* __restrict__ out)
{
    const int row = blockIdx.x, tid = threadIdx.x;
    __shared__ float red[256];
    float x = a[row * DM + tid] + b[row * DM + tid];
    red[tid] = x; __syncthreads();
    #pragma unroll
    for (int s = 128; s > 0; s >>= 1) { if (tid < s) red[tid] += red[tid + s]; __syncthreads(); }
    float mean = red[0] * (1.f / DM); __syncthreads();
    float d = x - mean;
    red[tid] = d * d; __syncthreads();
    #pragma unroll
    for (int s = 128; s > 0; s >>= 1) { if (tid < s) red[tid] += red[tid + s]; __syncthreads(); }
    float var = red[0] * (1.f / DM);
    out[row * DM + tid] = d * rsqrtf(var + 1e-6f) * g[tid] + be[tid];
}

// ---------------- launch ----------------
extern "C" void kernel_launch(void* const* d_in, const int* in_sizes, int n_in,
                              void* d_out, int out_size)
{
    const float* sensor = (const float*)d_in[0];
    const float* query  = (const float*)d_in[1];
    const float* keyemb = (const float*)d_in[2];
    const float* qA     = (const float*)d_in[3];
    const float* kA     = (const float*)d_in[4];
    const float* qco    = (const float*)d_in[5];
    const float* kco    = (const float*)d_in[6];
    const int*   qiso   = (const int*)d_in[7];
    const int*   kiso   = (const int*)d_in[8];
    const float* g1w    = (const float*)d_in[9];
    const float* g1b    = (const float*)d_in[10];
    const float* g2w    = (const float*)d_in[11];
    const float* g2b    = (const float*)d_in[12];
    const float* h1w    = (const float*)d_in[13];
    const float* h1b    = (const float*)d_in[14];
    const float* h2w    = (const float*)d_in[15];
    const float* h2b    = (const float*)d_in[16];
    const float* f1w    = (const float*)d_in[17];
    const float* f1b    = (const float*)d_in[18];
    const float* f2w    = (const float*)d_in[19];
    const float* f2b    = (const float*)d_in[20];
    const float* ln1g   = (const float*)d_in[21];
    const float* ln1b   = (const float*)d_in[22];
    const float* ln2g   = (const float*)d_in[23];
    const float* ln2b   = (const float*)d_in[24];
    float* out = (float*)d_out;

    float *pR, *pL, *pAO, *pX, *pF1, *pF2;
    cudaGetSymbolAddress((void**)&pR,  g_R);
    cudaGetSymbolAddress((void**)&pL,  g_L);
    cudaGetSymbolAddress((void**)&pAO, g_AO);
    cudaGetSymbolAddress((void**)&pX,  g_X);
    cudaGetSymbolAddress((void**)&pF1, g_F1);
    cudaGetSymbolAddress((void**)&pF2, g_F2);

    // 1) fused transposed reductions over N=65536 (the HBM-bound pass)
    reduce_k<<<dim3(RBLK, 2), 256>>>(qA, kA, qco, kco, qiso, kiso);
    reduce2_k<<<(2 * 15 * K_CL) / 256, 256>>>();

    // 2) per-cluster features + factorized MLP layer-1 partials
    cfeat_k<<<K_CL / 256, 256>>>(sensor, g1w, g1b, h1w, h1b);

    // 3) R factor over all KxK pairs
    rfactor_k<<<dim3(16, 16), 256>>>(g2w, g2b, h2w, h2b, h1w);

    // 4) logits = (Q @ K^T) / 16 * R
    gemm_k<128, 64, 1, true><<<dim3(16, 8), 256>>>(query, keyemb, pL, K_CL, K_CL, DM, pR, 0.0625f);

    // 5) softmax rows
    softmax_k<<<K_CL, 256>>>(pL);

    // 6) attn @ key_emb
    gemm_k<32, 64, 0, false><<<dim3(4, 32), 256>>>(pL, keyemb, pAO, K_CL, DM, K_CL, nullptr, 1.f);

    // 7) x = LN1(query + attn_out)
    add_ln_k<<<K_CL, 256>>>(query, pAO, ln1g, ln1b, pX);

    // 8) FFN1: relu(x @ w1 + b1)
    gemm_k<128, 64, 2, false><<<dim3(16, 8), 256>>>(pX, f1w, pF1, K_CL, 4 * DM, DM, f1b, 1.f);

    // 9) FFN2: h @ w2 + b2
    gemm_k<32, 64, 3, false><<<dim3(4, 32), 256>>>(pF1, f2w, pF2, K_CL, DM, 4 * DM, f2b, 1.f);

    // 10) out = LN2(x + ffn)
    add_ln_k<<<K_CL, 256>>>(pX, pF2, ln2g, ln2b, out);
}

// round 4
// speedup vs baseline: 1.0765x; 1.0400x over previous
#include <cuda_runtime.h>
#include <math.h>
#include <stdint.h>

#define K_CL 1024
#define DM   256
#define NPX  65536
#define NISO 12
#define RBLK 304
#define CHUNK 216

typedef unsigned long long u64;

__device__ __forceinline__ u64 pack2(float lo, float hi) {
    u64 r;
    asm("mov.b64 %0, {%1, %2};" : "=l"(r)
        : "r"(__float_as_uint(lo)), "r"(__float_as_uint(hi)));
    return r;
}
__device__ __forceinline__ void unpack2(u64 v, float& lo, float& hi) {
    unsigned a, b;
    asm("mov.b64 {%0, %1}, %2;" : "=r"(a), "=r"(b) : "l"(v));
    lo = __uint_as_float(a); hi = __uint_as_float(b);
}
__device__ __forceinline__ u64 fma2(u64 a, u64 b, u64 c) {
    u64 d;
    asm("fma.rn.f32x2 %0, %1, %2, %3;" : "=l"(d) : "l"(a), "l"(b), "l"(c));
    return d;
}

// ---------------- device scratch ----------------
__device__ float g_part[2 * RBLK * 15 * K_CL];
__device__ float g_S[2 * 15 * K_CL];
__device__ float g_GU[K_CL * 32];
__device__ float g_GV[K_CL * 32];
__device__ float g_HA[K_CL * 32];
__device__ float g_HB[K_CL * 32];
__device__ float g_QC[K_CL * 2];
__device__ float g_KC[K_CL * 2];
__device__ float g_R[K_CL * K_CL];
__device__ float g_L[K_CL * K_CL];
__device__ float g_AO[K_CL * DM];
__device__ float g_X[K_CL * DM];
__device__ float g_F1[K_CL * 4 * DM];
__device__ float g_F2[K_CL * DM];

// ---------------- kernel 1: fused A^T reductions (HBM bound) ----------------
__launch_bounds__(256)
__global__ void reduce_k(const float* __restrict__ qA, const float* __restrict__ kA,
                         const float* __restrict__ qco, const float* __restrict__ kco,
                         const int* __restrict__ qiso, const int* __restrict__ kiso)
{
    __shared__ float4 sIso[NISO * 256];   // 48KB
    const int tid = threadIdx.x;
    const int bx  = blockIdx.x;
    const int mat = blockIdx.y;
    const float* __restrict__ A   = mat ? kA   : qA;
    const float2* __restrict__ co2 = (const float2*)(mat ? kco : qco);
    const int*   __restrict__ iso = mat ? kiso : qiso;

    for (int i = tid; i < NISO * 256; i += 256) sIso[i] = make_float4(0.f, 0.f, 0.f, 0.f);
    __syncthreads();

    float4 sx = make_float4(0,0,0,0), sy = sx, ss = sx;

    const int base = bx * CHUNK;
    const int end  = (base + CHUNK < NPX) ? base + CHUNK : NPX;
    const float4* __restrict__ A4 = (const float4*)A;

    for (int r = base; r < end; r += 4) {
        // 4 independent loads in flight
        float4 a0 = A4[(size_t)(r+0) * 256 + tid];
        float4 a1 = A4[(size_t)(r+1) * 256 + tid];
        float4 a2 = A4[(size_t)(r+2) * 256 + tid];
        float4 a3 = A4[(size_t)(r+3) * 256 + tid];
        float2 c0 = __ldg(co2 + r+0), c1 = __ldg(co2 + r+1);
        float2 c2 = __ldg(co2 + r+2), c3 = __ldg(co2 + r+3);
        int i0 = __ldg(iso + r+0) - 1, i1 = __ldg(iso + r+1) - 1;
        int i2 = __ldg(iso + r+2) - 1, i3 = __ldg(iso + r+3) - 1;

        #define ACC(a, c, ic) do { \
            sx.x = fmaf(a.x, c.x, sx.x); sx.y = fmaf(a.y, c.x, sx.y); \
            sx.z = fmaf(a.z, c.x, sx.z); sx.w = fmaf(a.w, c.x, sx.w); \
            sy.x = fmaf(a.x, c.y, sy.x); sy.y = fmaf(a.y, c.y, sy.y); \
            sy.z = fmaf(a.z, c.y, sy.z); sy.w = fmaf(a.w, c.y, sy.w); \
            ss.x += a.x; ss.y += a.y; ss.z += a.z; ss.w += a.w; \
            float4 t = sIso[(ic) * 256 + tid]; \
            t.x += a.x; t.y += a.y; t.z += a.z; t.w += a.w; \
            sIso[(ic) * 256 + tid] = t; } while (0)

        ACC(a0, c0, i0); ACC(a1, c1, i1); ACC(a2, c2, i2); ACC(a3, c3, i3);
        #undef ACC
    }

    float4* P4 = (float4*)(g_part + (size_t)(mat * RBLK + bx) * 15 * K_CL);
    P4[0 * 256 + tid] = sx;
    P4[1 * 256 + tid] = sy;
    P4[2 * 256 + tid] = ss;
    #pragma unroll
    for (int c = 0; c < NISO; c++)
        P4[(3 + c) * 256 + tid] = sIso[c * 256 + tid];
}

// ---------------- kernel 2: reduce partials ----------------
__global__ void reduce2_k()
{
    int idx = blockIdx.x * 256 + threadIdx.x;
    int mat = idx / (15 * K_CL);
    int rem = idx % (15 * K_CL);
    const float* P = g_part + (size_t)mat * RBLK * 15 * K_CL + rem;
    float s = 0.f;
    #pragma unroll 8
    for (int b = 0; b < RBLK; b++) s += P[(size_t)b * 15 * K_CL];
    g_S[idx] = s;
}

// ---------------- kernel 3: per-cluster features ----------------
__global__ void cfeat_k(const float* __restrict__ sensor,
                        const float* __restrict__ g1w, const float* __restrict__ g1b,
                        const float* __restrict__ h1w, const float* __restrict__ h1b)
{
    int k = blockIdx.x * 256 + threadIdx.x;
    float dq[NISO], dkp[NISO];

    float sq  = g_S[(0*15 + 2)*K_CL + k];
    float qcx = g_S[(0*15 + 0)*K_CL + k] / (sq + 1e-6f);
    float qcy = g_S[(0*15 + 1)*K_CL + k] / (sq + 1e-6f);
    float sk  = g_S[(1*15 + 2)*K_CL + k];
    float kcx = g_S[(1*15 + 0)*K_CL + k] / (sk + 1e-6f);
    float kcy = g_S[(1*15 + 1)*K_CL + k] / (sk + 1e-6f);

    float sum0 = 0.f, sum1 = 0.f;
    #pragma unroll
    for (int c = 0; c < NISO; c++) {
        dq[c]  = g_S[(0*15 + 3 + c)*K_CL + k];  sum0 += dq[c];
        dkp[c] = g_S[(1*15 + 3 + c)*K_CL + k];  sum1 += dkp[c];
    }
    #pragma unroll
    for (int c = 0; c < NISO; c++) { dq[c] /= sum0; dkp[c] /= sum1; }

    float sxn = sensor[0], syn = sensor[1];
    float nks  = sqrtf((qcx - sxn)*(qcx - sxn) + (qcy - syn)*(qcy - syn));
    float nkps = sqrtf((kcx - sxn)*(kcx - sxn) + (kcy - syn)*(kcy - syn));

    g_QC[2*k] = qcx; g_QC[2*k+1] = qcy;
    g_KC[2*k] = kcx; g_KC[2*k+1] = kcy;

    for (int o = 0; o < 32; o++) {
        float u = g1b[o], v = 0.f;
        #pragma unroll
        for (int c = 0; c < NISO; c++) {
            u = fmaf(dq[c],  g1w[c*32 + o],          u);
            v = fmaf(dkp[c], g1w[(NISO + c)*32 + o], v);
        }
        g_GU[k*32 + o] = u;
        g_GV[k*32 + o] = v;
        g_HA[k*32 + o] = fmaf(nks, h1w[32 + o], h1b[o]);
        g_HB[k*32 + o] = nkps * h1w[64 + o];
    }
}

// ---------------- kernel 4: R factor (transposed smem tiles) ----------------
__launch_bounds__(256)
__global__ void rfactor_k(const float* __restrict__ g2w, const float* __restrict__ g2b,
                          const float* __restrict__ h2w, const float* __restrict__ h2b,
                          const float* __restrict__ h1w)
{
    __shared__ float sGU[32][68], sGV[32][68], sHA[32][68], sHB[32][68];  // [c][row]
    __shared__ float sW[96];
    __shared__ float sQC[64][2], sKC[64][2];

    const int tid = threadIdx.x;
    const int ib = blockIdx.y * 64, jb = blockIdx.x * 64;

    #pragma unroll
    for (int p = 0; p < 2; p++) {
        int idx = tid + p * 256;
        int row = idx >> 3, c0 = (idx & 7) * 4;
        float4 u = *(const float4*)&g_GU[(ib + row)*32 + c0];
        sGU[c0][row] = u.x; sGU[c0+1][row] = u.y; sGU[c0+2][row] = u.z; sGU[c0+3][row] = u.w;
        float4 v = *(const float4*)&g_GV[(jb + row)*32 + c0];
        sGV[c0][row] = v.x; sGV[c0+1][row] = v.y; sGV[c0+2][row] = v.z; sGV[c0+3][row] = v.w;
        float4 a = *(const float4*)&g_HA[(ib + row)*32 + c0];
        sHA[c0][row] = a.x; sHA[c0+1][row] = a.y; sHA[c0+2][row] = a.z; sHA[c0+3][row] = a.w;
        float4 b = *(const float4*)&g_HB[(jb + row)*32 + c0];
        sHB[c0][row] = b.x; sHB[c0+1][row] = b.y; sHB[c0+2][row] = b.z; sHB[c0+3][row] = b.w;
    }
    if (tid < 32)       sW[tid] = g2w[tid];
    else if (tid < 64)  sW[tid] = h2w[tid - 32];
    else if (tid < 96)  sW[tid] = h1w[tid - 64];
    if (tid < 128)      sQC[tid >> 1][tid & 1] = g_QC[(ib + (tid >> 1))*2 + (tid & 1)];
    else                { int t = tid - 128; sKC[t >> 1][t & 1] = g_KC[(jb + (t >> 1))*2 + (t & 1)]; }
    __syncthreads();

    const int ty = tid >> 4, tx = tid & 15;
    float nkk[4][4];
    #pragma unroll
    for (int m = 0; m < 4; m++) {
        float qx = sQC[ty*4 + m][0], qy = sQC[ty*4 + m][1];
        #pragma unroll
        for (int n = 0; n < 4; n++) {
            float dx = qx - sKC[tx*4 + n][0], dy = qy - sKC[tx*4 + n][1];
            nkk[m][n] = sqrtf(dx*dx + dy*dy);
        }
    }

    float gacc[4][4], hacc[4][4];
    #pragma unroll
    for (int m = 0; m < 4; m++)
        #pragma unroll
        for (int n = 0; n < 4; n++) { gacc[m][n] = 0.f; hacc[m][n] = 0.f; }

    #pragma unroll 4
    for (int c = 0; c < 32; c++) {
        float gw = sW[c], hw = sW[32 + c], w1c = sW[64 + c];
        float4 au = *(const float4*)&sGU[c][ty*4];
        float4 aa = *(const float4*)&sHA[c][ty*4];
        float4 bv = *(const float4*)&sGV[c][tx*4];
        float4 bb = *(const float4*)&sHB[c][tx*4];
        const float* aup = &au.x; const float* aap = &aa.x;
        const float* bvp = &bv.x; const float* bbp = &bb.x;
        #pragma unroll
        for (int m = 0; m < 4; m++)
            #pragma unroll
            for (int n = 0; n < 4; n++) {
                float g = fmaxf(aup[m] + bvp[n], 0.f);
                gacc[m][n] = fmaf(g, gw, gacc[m][n]);
                float h = fmaxf(fmaf(nkk[m][n], w1c, aap[m] + bbp[n]), 0.f);
                hacc[m][n] = fmaf(h, hw, hacc[m][n]);
            }
    }

    const float g2b0 = g2b[0], h2b0 = h2b[0];
    #pragma unroll
    for (int m = 0; m < 4; m++) {
        float4 o;
        float* op = &o.x;
        #pragma unroll
        for (int n = 0; n < 4; n++)
            op[n] = fmaxf(gacc[m][n] + g2b0, 0.f) * fmaxf(hacc[m][n] + h2b0, 0.f);
        *(float4*)&g_R[(size_t)(ib + ty*4 + m) * K_CL + jb + tx*4] = o;
    }
}

// ---------------- pipelined f32x2 GEMM ----------------
// C(MxN) = A @ op(B). TN=64 fixed. 256 threads, thread (ty,tx) 16x16,
// RM = TM/16 rows x 4 cols per thread. Double-buffered smem, 1 sync/tile.
// MODE 0: store; 1: *scale*ext[i*N+j]; 2: relu(+ext[j]); 3: +ext[j].
template<int TM, int MODE, bool BT>
__launch_bounds__(256)
__global__ void gemm_k2(const float* __restrict__ A, const float* __restrict__ B,
                        float* __restrict__ C, int M, int N, int Kd,
                        const float* __restrict__ ext, float scale)
{
    constexpr int TN = 64;
    constexpr int RM = TM / 16;
    constexpr int NA = (TM * 4 + 255) / 256;
    __shared__ float As[2][16][TM];
    __shared__ float Bs[2][16][TN];

    const int tid = threadIdx.x;
    const int tx = tid & 15, ty = tid >> 4;
    const int row0 = blockIdx.y * TM, col0 = blockIdx.x * TN;

    float4 ra[NA];
    float4 rb;

    auto ldTile = [&](int k0) {
        #pragma unroll
        for (int i = 0; i < NA; i++) {
            int idx = tid + i * 256;
            if ((TM * 4) % 256 == 0 || idx < TM * 4) {
                int lr = idx >> 2, lc = (idx & 3) * 4;
                ra[i] = *(const float4*)(A + (size_t)(row0 + lr) * Kd + k0 + lc);
            }
        }
        if (BT) {
            int lr = tid >> 2, lc = (tid & 3) * 4;
            rb = *(const float4*)(B + (size_t)(col0 + lr) * Kd + k0 + lc);
        } else {
            int lr = tid >> 4, lc = (tid & 15) * 4;
            rb = *(const float4*)(B + (size_t)(k0 + lr) * N + col0 + lc);
        }
    };
    auto stTile = [&](int buf) {
        #pragma unroll
        for (int i = 0; i < NA; i++) {
            int idx = tid + i * 256;
            if ((TM * 4) % 256 == 0 || idx < TM * 4) {
                int lr = idx >> 2, lc = (idx & 3) * 4;
                As[buf][lc+0][lr] = ra[i].x; As[buf][lc+1][lr] = ra[i].y;
                As[buf][lc+2][lr] = ra[i].z; As[buf][lc+3][lr] = ra[i].w;
            }
        }
        if (BT) {
            int lr = tid >> 2, lc = (tid & 3) * 4;
            Bs[buf][lc+0][lr] = rb.x; Bs[buf][lc+1][lr] = rb.y;
            Bs[buf][lc+2][lr] = rb.z; Bs[buf][lc+3][lr] = rb.w;
        } else {
            int lr = tid >> 4, lc = (tid & 15) * 4;
            *(float4*)&Bs[buf][lr][lc] = rb;
        }
    };

    u64 acc[RM][2];
    #pragma unroll
    for (int m = 0; m < RM; m++) { acc[m][0] = 0ULL; acc[m][1] = 0ULL; }

    const int nt = Kd >> 4;
    ldTile(0);
    stTile(0);
    __syncthreads();

    for (int t = 0; t < nt; t++) {
        const int cur = t & 1;
        if (t + 1 < nt) ldTile((t + 1) << 4);

        #pragma unroll
        for (int kk = 0; kk < 16; kk++) {
            float a[RM];
            if constexpr (RM == 8) {
                float4 t0 = *(const float4*)&As[cur][kk][ty * 8];
                float4 t1 = *(const float4*)&As[cur][kk][ty * 8 + 4];
                a[0]=t0.x; a[1]=t0.y; a[2]=t0.z; a[3]=t0.w;
                a[4]=t1.x; a[5]=t1.y; a[6]=t1.z; a[7]=t1.w;
            } else {
                float2 t0 = *(const float2*)&As[cur][kk][ty * 2];
                a[0]=t0.x; a[1]=t0.y;
            }
            u64 b0 = *(const u64*)&Bs[cur][kk][tx * 4];
            u64 b1 = *(const u64*)&Bs[cur][kk][tx * 4 + 2];
            #pragma unroll
            for (int m = 0; m < RM; m++) {
                u64 aa = pack2(a[m], a[m]);
                acc[m][0] = fma2(aa, b0, acc[m][0]);
                acc[m][1] = fma2(aa, b1, acc[m][1]);
            }
        }

        if (t + 1 < nt) {
            stTile((t + 1) & 1);
            __syncthreads();
        }
    }

    #pragma unroll
    for (int m = 0; m < RM; m++) {
        int i = row0 + ty * RM + m;
        int j0 = col0 + tx * 4;
        float v0, v1, v2, v3;
        unpack2(acc[m][0], v0, v1);
        unpack2(acc[m][1], v2, v3);
        if (MODE == 1) {
            float4 r = *(const float4*)(ext + (size_t)i * N + j0);
            v0 = v0 * scale * r.x; v1 = v1 * scale * r.y;
            v2 = v2 * scale * r.z; v3 = v3 * scale * r.w;
        } else if (MODE == 2) {
            v0 = fmaxf(v0 + ext[j0+0], 0.f); v1 = fmaxf(v1 + ext[j0+1], 0.f);
            v2 = fmaxf(v2 + ext[j0+2], 0.f); v3 = fmaxf(v3 + ext[j0+3], 0.f);
        } else if (MODE == 3) {
            v0 += ext[j0+0]; v1 += ext[j0+1]; v2 += ext[j0+2]; v3 += ext[j0+3];
        }
        float4 o; o.x = v0; o.y = v1; o.z = v2; o.w = v3;
        *(float4*)(C + (size_t)i * N + j0) = o;
    }
}

// ---------------- softmax ----------------
__global__ void softmax_k(float* __restrict__ X)
{
    const int row = blockIdx.x, tid = threadIdx.x;
    __shared__ float red[256];
    float v[4];
    float m = -3.4e38f;
    #pragma unroll
    for (int j = 0; j < 4; j++) { v[j] = X[(size_t)row * K_CL + tid + j * 256]; m = fmaxf(m, v[j]); }
    red[tid] = m; __syncthreads();
    #pragma unroll
    for (int s = 128; s > 0; s >>= 1) { if (tid < s) red[tid] = fmaxf(red[tid], red[tid + s]); __syncthreads(); }
    m = red[0]; __syncthreads();
    float sum = 0.f;
    #pragma unroll
    for (int j = 0; j < 4; j++) { v[j] = __expf(v[j] - m); sum += v[j]; }
    red[tid] = sum; __syncthreads();
    #pragma unroll
    for (int s = 128; s > 0; s >>= 1) { if (tid < s) red[tid] += red[tid + s]; __syncthreads(); }
    float inv = 1.f / red[0];
    #pragma unroll
    for (int j = 0; j < 4; j++) X[(size_t)row * K_CL + tid + j * 256] = v[j] * inv;
}

// ---------------- residual add + LayerNorm ----------------
__global__ void add_ln_k(const float* __restrict__ a, const float* __restrict__ b,
                         const float* __restrict__ g, const float* __restrict__ be,
                         float* __restrict__ out)
{
    const int row = blockIdx.x, tid = threadIdx.x;
    __shared__ float red[256];
    float x = a[row * DM + tid] + b[row * DM + tid];
    red[tid] = x; __syncthreads();
    #pragma unroll
    for (int s = 128; s > 0; s >>= 1) { if (tid < s) red[tid] += red[tid + s]; __syncthreads(); }
    float mean = red[0] * (1.f / DM); __syncthreads();
    float d = x - mean;
    red[tid] = d * d; __syncthreads();
    #pragma unroll
    for (int s = 128; s > 0; s >>= 1) { if (tid < s) red[tid] += red[tid + s]; __syncthreads(); }
    float var = red[0] * (1.f / DM);
    out[row * DM + tid] = d * rsqrtf(var + 1e-6f) * g[tid] + be[tid];
}

// ---------------- launch ----------------
extern "C" void kernel_launch(void* const* d_in, const int* in_sizes, int n_in,
                              void* d_out, int out_size)
{
    const float* sensor = (const float*)d_in[0];
    const float* query  = (const float*)d_in[1];
    const float* keyemb = (const float*)d_in[2];
    const float* qA     = (const float*)d_in[3];
    const float* kA     = (const float*)d_in[4];
    const float* qco    = (const float*)d_in[5];
    const float* kco    = (const float*)d_in[6];
    const int*   qiso   = (const int*)d_in[7];
    const int*   kiso   = (const int*)d_in[8];
    const float* g1w    = (const float*)d_in[9];
    const float* g1b    = (const float*)d_in[10];
    const float* g2w    = (const float*)d_in[11];
    const float* g2b    = (const float*)d_in[12];
    const float* h1w    = (const float*)d_in[13];
    const float* h1b    = (const float*)d_in[14];
    const float* h2w    = (const float*)d_in[15];
    const float* h2b    = (const float*)d_in[16];
    const float* f1w    = (const float*)d_in[17];
    const float* f1b    = (const float*)d_in[18];
    const float* f2w    = (const float*)d_in[19];
    const float* f2b    = (const float*)d_in[20];
    const float* ln1g   = (const float*)d_in[21];
    const float* ln1b   = (const float*)d_in[22];
    const float* ln2g   = (const float*)d_in[23];
    const float* ln2b   = (const float*)d_in[24];
    float* out = (float*)d_out;

    float *pR, *pL, *pAO, *pX, *pF1, *pF2;
    cudaGetSymbolAddress((void**)&pR,  g_R);
    cudaGetSymbolAddress((void**)&pL,  g_L);
    cudaGetSymbolAddress((void**)&pAO, g_AO);
    cudaGetSymbolAddress((void**)&pX,  g_X);
    cudaGetSymbolAddress((void**)&pF1, g_F1);
    cudaGetSymbolAddress((void**)&pF2, g_F2);

    reduce_k<<<dim3(RBLK, 2), 256>>>(qA, kA, qco, kco, qiso, kiso);
    reduce2_k<<<(2 * 15 * K_CL) / 256, 256>>>();
    cfeat_k<<<K_CL / 256, 256>>>(sensor, g1w, g1b, h1w, h1b);
    rfactor_k<<<dim3(16, 16), 256>>>(g2w, g2b, h2w, h2b, h1w);

    // logits = (Q @ K^T)/16 * R
    gemm_k2<128, 1, true><<<dim3(16, 8), 256>>>(query, keyemb, pL, K_CL, K_CL, DM, pR, 0.0625f);
    softmax_k<<<K_CL, 256>>>(pL);
    // attn @ key_emb
    gemm_k2<32, 0, false><<<dim3(4, 32), 256>>>(pL, keyemb, pAO, K_CL, DM, K_CL, nullptr, 1.f);
    add_ln_k<<<K_CL, 256>>>(query, pAO, ln1g, ln1b, pX);
    // FFN1
    gemm_k2<128, 2, false><<<dim3(16, 8), 256>>>(pX, f1w, pF1, K_CL, 4 * DM, DM, f1b, 1.f);
    // FFN2
    gemm_k2<32, 3, false><<<dim3(4, 32), 256>>>(pF1, f2w, pF2, K_CL, DM, 4 * DM, f2b, 1.f);
    add_ln_k<<<K_CL, 256>>>(pX, pF2, ln2g, ln2b, out);
}